// round 12
// baseline (speedup 1.0000x reference)
#include <cuda_runtime.h>
#include <stdint.h>

// RadialTokenizer — quarter-image fused quantize + chunked in-smem gather.
// bin = floor((x*0.5+0.5)*255)-127 in [0,127].
// Block = (image, quarter of 64 rows). Phase A: coalesced float4 stream ->
// 16KB smem bin bytes. Phase B: warp w processes an equal 1/8 chunk of the
// quarter's concatenated ring list (per-lane byte hists, conflict-free,
// no smem atomics); per ring segment it merges 128 u32 counts into a global
// per-(image,ring) histogram via atomicAdd. k_stats computes mean/std/median
// from the exact merged histograms.

#define HH 256
#define WW 256
#define NR 16
#define RS 3072          // slot stride per (quarter, ring); max count ~1.6K

__device__ int g_cnt2[64];                        // cursors per (q, r)
__device__ __align__(128) uint16_t g_off2[64 * RS];  // local (y&63)<<8|x offsets
__device__ int g_cum[4 * 17];                     // per-quarter ring prefix
__device__ unsigned int g_hist[768 * 16 * 128];   // merged histograms (6.3MB)

// ring i <=> 64*i^2 < d2 <= 64*(i+1)^2 ; center pixel excluded.
__device__ __forceinline__ int ring_of(int x, int y) {
    int dx = x - 128, dy = y - 128;
    int d2 = dx * dx + dy * dy;
    if (d2 == 0 || d2 > 16384) return -1;
    int i = (int)(__fmul_rn(sqrtf((float)d2), 0.125f) + 0.999f) - 1;
    if (i < 0) i = 0;
    while (i > 0 && 64 * i * i >= d2) i--;
    while (d2 > 64 * (i + 1) * (i + 1)) i++;
    return i;
}

// ---------------- init kernels (deterministic, every launch) ----------------

__global__ void k_zero2() {
    if (threadIdx.x < 64) g_cnt2[threadIdx.x] = 0;
}

// block = one row; build (quarter, ring) lists with warp-aggregated ranks +
// one atomic base per (row, ring). Order within a ring is irrelevant.
__global__ void k_build2() {
    __shared__ int wcnt[8][NR];
    __shared__ int wbase[8][NR];
    __shared__ int bbase[NR];
    int x = threadIdx.x, y = blockIdx.x;
    int lane = x & 31, w = x >> 5;
    int q = y >> 6;
    int r = ring_of(x, y);
    unsigned m = __match_any_sync(0xffffffffu, r);
    int rank = __popc(m & ((1u << lane) - 1));
    if (x < 128) ((int*)wcnt)[x] = 0;
    __syncthreads();
    if (r >= 0 && rank == 0) wcnt[w][r] = __popc(m);
    __syncthreads();
    if (x < NR) {
        int run = 0;
        #pragma unroll
        for (int ww = 0; ww < 8; ww++) { wbase[ww][x] = run; run += wcnt[ww][x]; }
        bbase[x] = run ? atomicAdd(&g_cnt2[q * NR + x], run) : 0;
    }
    __syncthreads();
    if (r >= 0) {
        int pos = bbase[r] + wbase[w][r] + rank;
        g_off2[(q * NR + r) * RS + pos] = (uint16_t)(((y & 63) << 8) | x);
    }
}

__global__ void k_cum() {
    if (threadIdx.x == 0) {
        for (int q = 0; q < 4; q++) {
            int run = 0;
            g_cum[q * 17] = 0;
            for (int r = 0; r < NR; r++) {
                run += g_cnt2[q * NR + r];
                g_cum[q * 17 + r + 1] = run;
            }
        }
    }
}

// zero the global histograms: 393216 uint4, 1536 blocks x 256 thr x 1 store
__global__ void k_gz() {
    uint4 z; z.x = z.y = z.z = z.w = 0u;
    ((uint4*)g_hist)[blockIdx.x * 256 + threadIdx.x] = z;
}

// ---------------- main kernel ----------------
// grid 3072 = image*4 quarters; 256 thr; dyn smem 49280B -> 4 blocks/SM.
// Hist byte addr = ((bin<<5)&0xF80) | (lane<<2) | (bin&3)  -> bank == lane.

__global__ void __launch_bounds__(256, 4) k_main(const float* __restrict__ img) {
    extern __shared__ __align__(16) uint8_t smem[];
    uint8_t* bins = smem;                       // 16KB
    uint8_t* hist = smem + 16384;               // 8 x 4KB
    int* scum = (int*)(smem + 49152);           // 17 ints

    const int tid  = threadIdx.x;
    const int lane = tid & 31;
    const int w    = tid >> 5;
    const int bc   = blockIdx.x >> 2;
    const int q    = blockIdx.x & 3;

    if (tid < 17) scum[tid] = g_cum[q * 17 + tid];

    // zero hists (32KB)
    {
        uint4* hz = (uint4*)hist;
        uint4 z; z.x = z.y = z.z = z.w = 0u;
        #pragma unroll
        for (int k = 0; k < 8; k++) hz[tid + 256 * k] = z;
    }

    // ---- Phase A: coalesced stream of this quarter (16K px) ----
    const float4* __restrict__ ipv =
        (const float4*)(img + (size_t)bc * 65536 + q * 16384);
    uint32_t* binw = (uint32_t*)bins;
    #pragma unroll 4
    for (int k = 0; k < 16; k++) {
        int idx = k * 256 + tid;
        float4 p = __ldcs(&ipv[idx]);
        // bit-identical to ref: fma(x,0.5,0.5) (exact mul -> single rounding
        // equals (x*0.5)+0.5), then unfused *255, then floor.
        int b0 = __float2int_rd(__fmul_rn(__fmaf_rn(p.x, 0.5f, 0.5f), 255.0f)) - 127;
        int b1 = __float2int_rd(__fmul_rn(__fmaf_rn(p.y, 0.5f, 0.5f), 255.0f)) - 127;
        int b2 = __float2int_rd(__fmul_rn(__fmaf_rn(p.z, 0.5f, 0.5f), 255.0f)) - 127;
        int b3 = __float2int_rd(__fmul_rn(__fmaf_rn(p.w, 0.5f, 0.5f), 255.0f)) - 127;
        binw[idx] = (uint32_t)b0 | ((uint32_t)b1 << 8)
                  | ((uint32_t)b2 << 16) | ((uint32_t)b3 << 24);
    }
    __syncthreads();

    // ---- Phase B: equal 1/8 chunk of this quarter's ring-concatenated list ----
    uint8_t* h = hist + (w << 12);
    const int hb_lane = lane << 2;
    const int Lq = scum[16];
    int i = (w * Lq) >> 3;
    const int we = ((w + 1) * Lq) >> 3;
    int r = 0;
    while (scum[r + 1] <= i) r++;

    #pragma unroll 1
    while (i < we) {
        const int segEnd = (scum[r + 1] < we) ? scum[r + 1] : we;
        const int cnt = segEnd - i;
        if (cnt > 0) {
            const int segBase = scum[r];
            const uint16_t* __restrict__ lst = g_off2 + (q * NR + r) * RS;
            const int steps = (cnt + 31) >> 5;
            #pragma unroll 4
            for (int s = 0; s < steps; s++) {
                int idx = i + (s << 5) + lane;
                bool val = idx < segEnd;
                int rk = (val ? idx : (segEnd - 1)) - segBase;
                int v = bins[lst[rk]];
                if (val) h[((v << 5) & 0xF80) | hb_lane | (v & 3)] += 1;
            }
            __syncwarp();

            // reduce: lane l owns bins 4l..4l+3; sum byte cols of 32 lanes
            const uint32_t* hw = (const uint32_t*)h;
            uint32_t a02 = 0, a13 = 0;
            #pragma unroll
            for (int jj = 0; jj < 32; jj++) {
                int j = (jj + lane) & 31;
                uint32_t vv = hw[lane * 32 + j];
                a02 += vv & 0x00FF00FFu;
                a13 += (vv >> 8) & 0x00FF00FFu;
            }
            int h0 = (int)(a02 & 0xFFFFu), h2 = (int)(a02 >> 16);
            int h1 = (int)(a13 & 0xFFFFu), h3 = (int)(a13 >> 16);

            unsigned int* gh = g_hist + ((((unsigned)bc << 4) + r) << 7) + (lane << 2);
            if (h0) atomicAdd(gh,     (unsigned)h0);
            if (h1) atomicAdd(gh + 1, (unsigned)h1);
            if (h2) atomicAdd(gh + 2, (unsigned)h2);
            if (h3) atomicAdd(gh + 3, (unsigned)h3);
            __syncwarp();   // all reduce-reads done before rezero

            // rezero this warp's hist (each lane zeroes its own column)
            uint4* hz = (uint4*)h;
            uint4 z; z.x = z.y = z.z = z.w = 0u;
            #pragma unroll
            for (int k = 0; k < 8; k++) hz[k * 32 + lane] = z;
        }
        i = segEnd; r++;
    }
}

// ---------------- stats kernel ----------------
// grid 768, 128 thr; warp w -> rings w, w+4, w+8, w+12.

__global__ void __launch_bounds__(128) k_stats(float* __restrict__ out) {
    const int tid  = threadIdx.x;
    const int lane = tid & 31;
    const int w    = tid >> 5;
    const int bc   = blockIdx.x;
    const int b = bc / 3, c = bc - b * 3;

    #pragma unroll
    for (int k = 0; k < 4; k++) {
        const int ring = w + (k << 2);
        const uint4 qv = *(const uint4*)(g_hist
            + ((((unsigned)bc << 4) + ring) << 7) + (lane << 2));
        int h0 = (int)qv.x, h1 = (int)qv.y, h2 = (int)qv.z, h3 = (int)qv.w;

        const int b0 = lane * 4;
        int sl  = h0 + h1 + h2 + h3;
        int sb  = h0 * b0 + h1 * (b0 + 1) + h2 * (b0 + 2) + h3 * (b0 + 3);
        int sb2 = h0 * b0 * b0 + h1 * (b0 + 1) * (b0 + 1)
                + h2 * (b0 + 2) * (b0 + 2) + h3 * (b0 + 3) * (b0 + 3);

        int sumb  = __reduce_add_sync(0xffffffffu, sb);
        int sumb2 = __reduce_add_sync(0xffffffffu, sb2);

        int sc = sl;
        #pragma unroll
        for (int d = 1; d < 32; d <<= 1) {
            int t2 = __shfl_up_sync(0xffffffffu, sc, d);
            if (lane >= d) sc += t2;
        }
        int n  = __shfl_sync(0xffffffffu, sc, 31);
        int cb = sc - sl;

        int k1 = (n - 1) >> 1, k2 = n >> 1;
        int c1 = 1 << 30, c2 = 1 << 30;
        {
            int t1 = k1 + 1;
            if (cb < t1 && t1 <= sc) {
                if      (cb + h0 >= t1)           c1 = b0;
                else if (cb + h0 + h1 >= t1)      c1 = b0 + 1;
                else if (cb + h0 + h1 + h2 >= t1) c1 = b0 + 2;
                else                              c1 = b0 + 3;
            }
            int t2r = k2 + 1;
            if (cb < t2r && t2r <= sc) {
                if      (cb + h0 >= t2r)           c2 = b0;
                else if (cb + h0 + h1 >= t2r)      c2 = b0 + 1;
                else if (cb + h0 + h1 + h2 >= t2r) c2 = b0 + 2;
                else                               c2 = b0 + 3;
            }
        }
        int m1 = __reduce_min_sync(0xffffffffu, c1);
        int m2 = __reduce_min_sync(0xffffffffu, c2);

        if (lane == 0) {
            double dn = (double)n;
            double mb = (double)sumb / dn;
            double mean = 127.0 + mb;
            double var = (double)sumb2 / dn - mb * mb;
            double sd = sqrt(var > 0.0 ? var : 0.0);
            double med = 127.0 + 0.5 * (double)(m1 + m2);
            int o = b * (NR * 9) + ring * 9 + c;
            out[o]     = (float)mean;
            out[o + 3] = (float)sd;
            out[o + 6] = (float)med;
        }
    }
}

extern "C" void kernel_launch(void* const* d_in, const int* in_sizes, int n_in,
                              void* d_out, int out_size) {
    const float* img = (const float*)d_in[0];
    float* out = (float*)d_out;

    static int attr_set = 0;
    if (!attr_set) {
        cudaFuncSetAttribute(k_main, cudaFuncAttributeMaxDynamicSharedMemorySize,
                             49280);
        attr_set = 1;
    }

    k_zero2<<<1, 64>>>();
    k_build2<<<HH, WW>>>();
    k_cum<<<1, 32>>>();
    k_gz<<<1536, 256>>>();
    k_main<<<3072, 256, 49280>>>(img);
    k_stats<<<768, 128>>>(out);
}